// round 1
// baseline (speedup 1.0000x reference)
#include <cuda_runtime.h>
#include <math.h>

#define BATCH   4
#define SEQ     2048
#define DMODEL  512
#define NHEAD   8
#define HDIM    64
#define ROWS    (BATCH * SEQ)        /* 8192 */
#define QKVN    (3 * DMODEL)         /* 1536 */

// Scratch (allocation-free rule: device globals)
__device__ float g_qkv[(size_t)ROWS * QKVN];     // [8192, 1536]
__device__ float g_att[(size_t)ROWS * DMODEL];   // [8192, 512] == (B,H,S,hd) flat

// ---------------------------------------------------------------------------
// SGEMM: C[M,N] = A[M,K] @ B[K,N], all row-major. 128x128 tile, BK=8, 8x8/thr.
// ---------------------------------------------------------------------------
#define BM 128
#define BN 128
#define BKG 8
#define TM 8
#define TN 8

__global__ __launch_bounds__(256, 2)
void sgemm_kernel(const float* __restrict__ A, const float* __restrict__ B,
                  float* __restrict__ C, int M, int N, int K) {
    __shared__ float As[BKG][BM];   // A tile transposed: As[k][m]
    __shared__ float Bs[BKG][BN];

    const int tid = threadIdx.x;
    const int tx  = tid & 15;       // 16 col-groups
    const int ty  = tid >> 4;       // 16 row-groups

    // loaders
    const int aRow = tid >> 1;            // 0..127
    const int aCol = (tid & 1) << 2;      // 0 or 4
    const int bRow = tid >> 5;            // 0..7
    const int bCol = (tid & 31) << 2;     // 0..124

    const float* Ab = A + (size_t)blockIdx.y * BM * K;
    const float* Bb = B + (size_t)blockIdx.x * BN;

    float acc[TM][TN];
    #pragma unroll
    for (int i = 0; i < TM; i++)
        #pragma unroll
        for (int j = 0; j < TN; j++) acc[i][j] = 0.f;

    for (int k0 = 0; k0 < K; k0 += BKG) {
        float4 av = *(const float4*)(Ab + (size_t)aRow * K + k0 + aCol);
        As[aCol + 0][aRow] = av.x;
        As[aCol + 1][aRow] = av.y;
        As[aCol + 2][aRow] = av.z;
        As[aCol + 3][aRow] = av.w;
        *(float4*)&Bs[bRow][bCol] =
            *(const float4*)(Bb + (size_t)(k0 + bRow) * N + bCol);
        __syncthreads();

        #pragma unroll
        for (int k = 0; k < BKG; k++) {
            float4 a0 = *(const float4*)&As[k][ty * TM];
            float4 a1 = *(const float4*)&As[k][ty * TM + 4];
            float4 b0 = *(const float4*)&Bs[k][tx * TN];
            float4 b1 = *(const float4*)&Bs[k][tx * TN + 4];
            float ar[TM] = {a0.x, a0.y, a0.z, a0.w, a1.x, a1.y, a1.z, a1.w};
            float br[TN] = {b0.x, b0.y, b0.z, b0.w, b1.x, b1.y, b1.z, b1.w};
            #pragma unroll
            for (int i = 0; i < TM; i++)
                #pragma unroll
                for (int j = 0; j < TN; j++)
                    acc[i][j] = fmaf(ar[i], br[j], acc[i][j]);
        }
        __syncthreads();
    }

    float* Cb = C + (size_t)(blockIdx.y * BM + ty * TM) * N + blockIdx.x * BN + tx * TN;
    #pragma unroll
    for (int i = 0; i < TM; i++) {
        #pragma unroll
        for (int j = 0; j < TN; j += 4) {
            float4 v = make_float4(acc[i][j], acc[i][j+1], acc[i][j+2], acc[i][j+3]);
            *(float4*)(Cb + (size_t)i * N + j) = v;
        }
    }
}

// ---------------------------------------------------------------------------
// Masked flash attention over the reshaped layout.
// Per (b, h): Q/K/V are rows [h*2048, (h+1)*2048) of the [B,16384,192] view,
// cols 0:64 / 64:128 / 128:192. Block = 64 queries; stream 64-key tiles.
// grid (32, 8, 4), 256 threads as 16x16; each thread: 4 q-rows x 4 d/k-cols.
// Column mapping is strided (col = tx + 16*j) for conflict-free smem reads.
// ---------------------------------------------------------------------------
#define KPAD 65

__global__ __launch_bounds__(256, 3)
void attn_kernel(const float* __restrict__ qkv, const int* __restrict__ pmask,
                 float* __restrict__ attout) {
    extern __shared__ float sm[];
    float* Qs = sm;                    // [64][64]
    float* Ks = Qs + 64 * 64;          // [64][KPAD]
    float* Vs = Ks + 64 * KPAD;        // [64][64]
    float* Ps = Vs + 64 * 64;          // [64][KPAD]
    float* mk = Ps + 64 * KPAD;        // [64] additive mask (0 or -inf)

    const int qt = blockIdx.x, h = blockIdx.y, b = blockIdx.z;
    const int tid = threadIdx.x;
    const int tx = tid & 15, ty = tid >> 4;

    const size_t rbase = (size_t)b * (NHEAD * SEQ) + (size_t)h * SEQ; // row in [B*16384,192] view
    const float* qkv_b = qkv + rbase * (3 * HDIM);

    // tile loader mapping: 4 threads/row, 16 floats (4x float4) per thread
    const int lrow = tid >> 2;
    const int lcol = (tid & 3) << 4;

    // ---- load Q tile ----
    {
        const float* src = qkv_b + (size_t)(qt * 64 + lrow) * (3 * HDIM) + lcol;
        float* dst = &Qs[lrow * 64 + lcol];
        #pragma unroll
        for (int u = 0; u < 4; u++)
            *(float4*)(dst + 4 * u) = *(const float4*)(src + 4 * u);
    }

    float m[4], l[4], O[4][4];
    #pragma unroll
    for (int i = 0; i < 4; i++) {
        m[i] = -INFINITY; l[i] = 0.f;
        #pragma unroll
        for (int j = 0; j < 4; j++) O[i][j] = 0.f;
    }

    for (int kt = 0; kt < SEQ / 64; kt++) {
        __syncthreads();  // prev PV done (and Q load visible on first iter)

        // ---- load K, V tiles + mask ----
        {
            const float* srck = qkv_b + (size_t)(kt * 64 + lrow) * (3 * HDIM) + HDIM + lcol;
            const float* srcv = srck + HDIM;
            float* dk = &Ks[lrow * KPAD + lcol];
            float* dv = &Vs[lrow * 64 + lcol];
            #pragma unroll
            for (int u = 0; u < 4; u++) {
                float4 kv = *(const float4*)(srck + 4 * u);
                dk[4*u+0] = kv.x; dk[4*u+1] = kv.y; dk[4*u+2] = kv.z; dk[4*u+3] = kv.w;
                *(float4*)(dv + 4 * u) = *(const float4*)(srcv + 4 * u);
            }
            if (tid < 64)
                mk[tid] = (pmask[b * SEQ + kt * 64 + tid] != 0) ? 0.f : -INFINITY;
        }
        __syncthreads();

        // ---- scores S = Q K^T * scale + mask ----
        float s[4][4];
        #pragma unroll
        for (int i = 0; i < 4; i++)
            #pragma unroll
            for (int j = 0; j < 4; j++) s[i][j] = 0.f;

        #pragma unroll 8
        for (int d = 0; d < HDIM; d++) {
            float qr[4], kr[4];
            #pragma unroll
            for (int i = 0; i < 4; i++) qr[i] = Qs[(4 * ty + i) * 64 + d];
            #pragma unroll
            for (int j = 0; j < 4; j++) kr[j] = Ks[(tx + 16 * j) * KPAD + d];
            #pragma unroll
            for (int i = 0; i < 4; i++)
                #pragma unroll
                for (int j = 0; j < 4; j++)
                    s[i][j] = fmaf(qr[i], kr[j], s[i][j]);
        }
        #pragma unroll
        for (int i = 0; i < 4; i++)
            #pragma unroll
            for (int j = 0; j < 4; j++)
                s[i][j] = s[i][j] * 0.125f + mk[tx + 16 * j];

        // ---- online softmax update ----
        float rowscale[4];
        #pragma unroll
        for (int i = 0; i < 4; i++) {
            float tmax = fmaxf(fmaxf(s[i][0], s[i][1]), fmaxf(s[i][2], s[i][3]));
            #pragma unroll
            for (int o = 8; o >= 1; o >>= 1)
                tmax = fmaxf(tmax, __shfl_xor_sync(0xffffffffu, tmax, o));
            float mn = fmaxf(m[i], tmax);
            float sc = (mn == -INFINITY) ? 1.f : __expf(m[i] - mn);
            float rsum = 0.f;
            #pragma unroll
            for (int j = 0; j < 4; j++) {
                float p = (s[i][j] == -INFINITY) ? 0.f : __expf(s[i][j] - mn);
                Ps[(4 * ty + i) * KPAD + tx + 16 * j] = p;
                rsum += p;
            }
            #pragma unroll
            for (int o = 8; o >= 1; o >>= 1)
                rsum += __shfl_xor_sync(0xffffffffu, rsum, o);
            l[i] = l[i] * sc + rsum;
            m[i] = mn;
            rowscale[i] = sc;
        }
        #pragma unroll
        for (int i = 0; i < 4; i++)
            #pragma unroll
            for (int j = 0; j < 4; j++) O[i][j] *= rowscale[i];
        __syncthreads();

        // ---- O += P @ V ----
        #pragma unroll 8
        for (int k = 0; k < 64; k++) {
            float pr[4], vr[4];
            #pragma unroll
            for (int i = 0; i < 4; i++) pr[i] = Ps[(4 * ty + i) * KPAD + k];
            #pragma unroll
            for (int j = 0; j < 4; j++) vr[j] = Vs[k * 64 + tx + 16 * j];
            #pragma unroll
            for (int i = 0; i < 4; i++)
                #pragma unroll
                for (int j = 0; j < 4; j++)
                    O[i][j] = fmaf(pr[i], vr[j], O[i][j]);
        }
    }

    // ---- epilogue: normalize, apply query validity, store ----
    const size_t obase = (rbase + (size_t)qt * 64) * HDIM;
    #pragma unroll
    for (int i = 0; i < 4; i++) {
        const int r = 4 * ty + i;
        float inv = (l[i] > 0.f) ? (1.f / l[i]) : 0.f;
        if (pmask[b * SEQ + qt * 64 + r] == 0) inv = 0.f;
        #pragma unroll
        for (int j = 0; j < 4; j++)
            attout[obase + (size_t)r * HDIM + tx + 16 * j] = O[i][j] * inv;
    }
}

// ---------------------------------------------------------------------------
extern "C" void kernel_launch(void* const* d_in, const int* in_sizes, int n_in,
                              void* d_out, int out_size) {
    const float* x     = (const float*)d_in[0];
    // d_in[1] = mask (unused: reference takes the paded_mask path)
    const int*   pmask = (const int*)d_in[2];   // nonzero test also valid for f32 0/1
    const float* Wqkv  = (const float*)d_in[3];
    const float* Wout  = (const float*)d_in[4];
    float* out = (float*)d_out;

    float *qkv_p = nullptr, *att_p = nullptr;
    cudaGetSymbolAddress((void**)&qkv_p, g_qkv);
    cudaGetSymbolAddress((void**)&att_p, g_att);

    // attention dynamic smem: Qs + Ks + Vs + Ps + mk
    const int attn_smem = (64*64 + 64*KPAD + 64*64 + 64*KPAD + 64) * (int)sizeof(float);
    cudaFuncSetAttribute(attn_kernel, cudaFuncAttributeMaxDynamicSharedMemorySize, attn_smem);

    // 1) QKV = x @ W_qkv : [8192,512] @ [512,1536]
    sgemm_kernel<<<dim3(QKVN / BN, ROWS / BM), 256>>>(x, Wqkv, qkv_p, ROWS, QKVN, DMODEL);

    // 2) masked attention per (b, h') over the reshaped (flat) layout
    attn_kernel<<<dim3(SEQ / 64, NHEAD, BATCH), 256, attn_smem>>>(qkv_p, pmask, att_p);

    // 3) out = att @ W_out : [8192,512] @ [512,512]
    sgemm_kernel<<<dim3(DMODEL / BN, ROWS / BM), 256>>>(att_p, Wout, out, ROWS, DMODEL, DMODEL);
}

// round 3
// speedup vs baseline: 1.4756x; 1.4756x over previous
#include <cuda_runtime.h>
#include <math.h>
#include <stdint.h>

#define BATCH   4
#define SEQ     2048
#define DMODEL  512
#define NHEAD   8
#define HDIM    64
#define ROWS    (BATCH * SEQ)        /* 8192 */
#define QKVN    (3 * DMODEL)         /* 1536 */

// Scratch (allocation-free rule: device globals)
__device__ float g_qkv[(size_t)ROWS * QKVN];     // [8192, 1536]
__device__ float g_att[(size_t)ROWS * DMODEL];   // [8192, 512] == (B,H,S,hd) flat

// ---------------------------------------------------------------------------
// SGEMM (unchanged from R1): C[M,N] = A[M,K] @ B[K,N] fp32.
// ---------------------------------------------------------------------------
#define BM 128
#define BN 128
#define BKG 8
#define TM 8
#define TN 8

__global__ __launch_bounds__(256, 2)
void sgemm_kernel(const float* __restrict__ A, const float* __restrict__ B,
                  float* __restrict__ C, int M, int N, int K) {
    __shared__ float As[BKG][BM];
    __shared__ float Bs[BKG][BN];

    const int tid = threadIdx.x;
    const int tx  = tid & 15;
    const int ty  = tid >> 4;

    const int aRow = tid >> 1;
    const int aCol = (tid & 1) << 2;
    const int bRow = tid >> 5;
    const int bCol = (tid & 31) << 2;

    const float* Ab = A + (size_t)blockIdx.y * BM * K;
    const float* Bb = B + (size_t)blockIdx.x * BN;

    float acc[TM][TN];
    #pragma unroll
    for (int i = 0; i < TM; i++)
        #pragma unroll
        for (int j = 0; j < TN; j++) acc[i][j] = 0.f;

    for (int k0 = 0; k0 < K; k0 += BKG) {
        float4 av = *(const float4*)(Ab + (size_t)aRow * K + k0 + aCol);
        As[aCol + 0][aRow] = av.x;
        As[aCol + 1][aRow] = av.y;
        As[aCol + 2][aRow] = av.z;
        As[aCol + 3][aRow] = av.w;
        *(float4*)&Bs[bRow][bCol] =
            *(const float4*)(Bb + (size_t)(k0 + bRow) * N + bCol);
        __syncthreads();

        #pragma unroll
        for (int k = 0; k < BKG; k++) {
            float4 a0 = *(const float4*)&As[k][ty * TM];
            float4 a1 = *(const float4*)&As[k][ty * TM + 4];
            float4 b0 = *(const float4*)&Bs[k][tx * TN];
            float4 b1 = *(const float4*)&Bs[k][tx * TN + 4];
            float ar[TM] = {a0.x, a0.y, a0.z, a0.w, a1.x, a1.y, a1.z, a1.w};
            float br[TN] = {b0.x, b0.y, b0.z, b0.w, b1.x, b1.y, b1.z, b1.w};
            #pragma unroll
            for (int i = 0; i < TM; i++)
                #pragma unroll
                for (int j = 0; j < TN; j++)
                    acc[i][j] = fmaf(ar[i], br[j], acc[i][j]);
        }
        __syncthreads();
    }

    float* Cb = C + (size_t)(blockIdx.y * BM + ty * TM) * N + blockIdx.x * BN + tx * TN;
    #pragma unroll
    for (int i = 0; i < TM; i++) {
        #pragma unroll
        for (int j = 0; j < TN; j += 4) {
            float4 v = make_float4(acc[i][j], acc[i][j+1], acc[i][j+2], acc[i][j+3]);
            *(float4*)(Cb + (size_t)i * N + j) = v;
        }
    }
}

// ---------------------------------------------------------------------------
// TF32 tensor-core flash attention.
// Block = 128 threads (4 warps) handles 64 queries of one (b,h'); streams
// 64-key tiles. Warp w owns query rows [16w,16w+16). All operands staged in
// smem as pre-converted tf32 bit patterns (pad=72 -> conflict-free frags).
// P round-trips through smem warp-locally (reuses Q region).
// ---------------------------------------------------------------------------
#define PAD 72
#define ATT_SMEM_WORDS (3 * 64 * PAD + 64)

__device__ __forceinline__ uint32_t f2tf(float x) {
    uint32_t r;
    asm("cvt.rna.tf32.f32 %0, %1;" : "=r"(r) : "f"(x));
    return r;
}

__device__ __forceinline__ void mma_tf32(float c[4], const uint32_t a[4],
                                         uint32_t b0, uint32_t b1) {
    asm volatile(
        "mma.sync.aligned.m16n8k8.row.col.f32.tf32.tf32.f32 "
        "{%0,%1,%2,%3}, {%4,%5,%6,%7}, {%8,%9}, {%0,%1,%2,%3};"
        : "+f"(c[0]), "+f"(c[1]), "+f"(c[2]), "+f"(c[3])
        : "r"(a[0]), "r"(a[1]), "r"(a[2]), "r"(a[3]), "r"(b0), "r"(b1));
}

__global__ __launch_bounds__(128)
void attn_mma_kernel(const float* __restrict__ qkv, const int* __restrict__ pmask,
                     float* __restrict__ attout) {
    extern __shared__ uint32_t smu[];
    uint32_t* Qs = smu;                 // [64][PAD] tf32 bits; later reused as Ps
    uint32_t* Ks = Qs + 64 * PAD;       // [64][PAD]
    uint32_t* Vs = Ks + 64 * PAD;       // [64][PAD]
    float*    mk = (float*)(Vs + 64 * PAD);  // [64] additive mask

    const int qt = blockIdx.x, h = blockIdx.y, b = blockIdx.z;
    const int tid  = threadIdx.x;
    const int warp = tid >> 5;
    const int lane = tid & 31;
    const int g = lane >> 2;            // group id (row within frag)
    const int c = lane & 3;             // thread in group

    const size_t rbase = (size_t)b * (NHEAD * SEQ) + (size_t)h * SEQ;
    const float* qkv_b = qkv + rbase * (3 * HDIM);

    // tile loader mapping: 2 threads per row, 32 floats each
    const int lrow  = tid >> 1;
    const int lhalf = (tid & 1) * 32;

    // ---- stage Q tile as tf32 ----
    {
        const float* src = qkv_b + (size_t)(qt * 64 + lrow) * (3 * HDIM) + lhalf;
        uint32_t* dst = &Qs[lrow * PAD + lhalf];
        #pragma unroll
        for (int u = 0; u < 8; u++) {
            float4 v = *(const float4*)(src + 4 * u);
            dst[4*u+0] = f2tf(v.x); dst[4*u+1] = f2tf(v.y);
            dst[4*u+2] = f2tf(v.z); dst[4*u+3] = f2tf(v.w);
        }
    }
    __syncthreads();

    // ---- Q fragments (A-frags, 8 d-chunks) ----
    uint32_t qa[8][4];
    {
        const int r0 = warp * 16 + g;
        #pragma unroll
        for (int ch = 0; ch < 8; ch++) {
            qa[ch][0] = Qs[(r0    ) * PAD + ch * 8 + c    ];
            qa[ch][1] = Qs[(r0 + 8) * PAD + ch * 8 + c    ];
            qa[ch][2] = Qs[(r0    ) * PAD + ch * 8 + c + 4];
            qa[ch][3] = Qs[(r0 + 8) * PAD + ch * 8 + c + 4];
        }
    }

    float o[8][4];
    #pragma unroll
    for (int nf = 0; nf < 8; nf++)
        #pragma unroll
        for (int j = 0; j < 4; j++) o[nf][j] = 0.f;
    float m0 = -INFINITY, m1 = -INFINITY, l0 = 0.f, l1 = 0.f;

    uint32_t* Ps = Qs;  // reuse after Q frags are in registers

    for (int kt = 0; kt < SEQ / 64; kt++) {
        __syncthreads();   // prior-iteration reads of Ks/Vs/mk complete

        // ---- stage K, V tiles (tf32) + mask ----
        {
            const float* srck = qkv_b + (size_t)(kt * 64 + lrow) * (3 * HDIM) + HDIM + lhalf;
            const float* srcv = srck + HDIM;
            uint32_t* dk = &Ks[lrow * PAD + lhalf];
            uint32_t* dv = &Vs[lrow * PAD + lhalf];
            #pragma unroll
            for (int u = 0; u < 8; u++) {
                float4 kv = *(const float4*)(srck + 4 * u);
                dk[4*u+0] = f2tf(kv.x); dk[4*u+1] = f2tf(kv.y);
                dk[4*u+2] = f2tf(kv.z); dk[4*u+3] = f2tf(kv.w);
                float4 vv = *(const float4*)(srcv + 4 * u);
                dv[4*u+0] = f2tf(vv.x); dv[4*u+1] = f2tf(vv.y);
                dv[4*u+2] = f2tf(vv.z); dv[4*u+3] = f2tf(vv.w);
            }
            if (tid < 64)
                mk[tid] = (pmask[b * SEQ + kt * 64 + tid] != 0) ? 0.f : -INFINITY;
        }
        __syncthreads();

        // ---- S = Q K^T (tf32 mma) ----
        float s[8][4];
        #pragma unroll
        for (int kg = 0; kg < 8; kg++) {
            s[kg][0] = s[kg][1] = s[kg][2] = s[kg][3] = 0.f;
            const uint32_t* kbase = &Ks[(kg * 8 + g) * PAD + c];
            #pragma unroll
            for (int ch = 0; ch < 8; ch++)
                mma_tf32(s[kg], qa[ch], kbase[ch * 8], kbase[ch * 8 + 4]);
        }

        // ---- scale + mask ----
        #pragma unroll
        for (int kg = 0; kg < 8; kg++) {
            const int col0 = kg * 8 + 2 * c;
            float mk0 = mk[col0], mk1 = mk[col0 + 1];
            s[kg][0] = s[kg][0] * 0.125f + mk0;
            s[kg][1] = s[kg][1] * 0.125f + mk1;
            s[kg][2] = s[kg][2] * 0.125f + mk0;
            s[kg][3] = s[kg][3] * 0.125f + mk1;
        }

        // ---- online softmax (rows g / g+8 of this warp) ----
        float mx0 = -INFINITY, mx1 = -INFINITY;
        #pragma unroll
        for (int kg = 0; kg < 8; kg++) {
            mx0 = fmaxf(mx0, fmaxf(s[kg][0], s[kg][1]));
            mx1 = fmaxf(mx1, fmaxf(s[kg][2], s[kg][3]));
        }
        mx0 = fmaxf(mx0, __shfl_xor_sync(0xffffffffu, mx0, 1));
        mx0 = fmaxf(mx0, __shfl_xor_sync(0xffffffffu, mx0, 2));
        mx1 = fmaxf(mx1, __shfl_xor_sync(0xffffffffu, mx1, 1));
        mx1 = fmaxf(mx1, __shfl_xor_sync(0xffffffffu, mx1, 2));

        float mn0 = fmaxf(m0, mx0), mn1 = fmaxf(m1, mx1);
        float sc0 = (mn0 == -INFINITY) ? 1.f : __expf(m0 - mn0);
        float sc1 = (mn1 == -INFINITY) ? 1.f : __expf(m1 - mn1);

        float sum0 = 0.f, sum1 = 0.f;
        {
            const int r0 = warp * 16 + g;
            uint32_t* pdst0 = &Ps[(r0    ) * PAD + 2 * c];
            uint32_t* pdst1 = &Ps[(r0 + 8) * PAD + 2 * c];
            #pragma unroll
            for (int kg = 0; kg < 8; kg++) {
                float p0 = (s[kg][0] == -INFINITY) ? 0.f : __expf(s[kg][0] - mn0);
                float p1 = (s[kg][1] == -INFINITY) ? 0.f : __expf(s[kg][1] - mn0);
                float p2 = (s[kg][2] == -INFINITY) ? 0.f : __expf(s[kg][2] - mn1);
                float p3 = (s[kg][3] == -INFINITY) ? 0.f : __expf(s[kg][3] - mn1);
                uint32_t t0 = f2tf(p0), t1 = f2tf(p1), t2 = f2tf(p2), t3 = f2tf(p3);
                // sum the tf32-rounded values so l matches the PV matmul exactly
                sum0 += __uint_as_float(t0) + __uint_as_float(t1);
                sum1 += __uint_as_float(t2) + __uint_as_float(t3);
                *(uint2*)(pdst0 + kg * 8) = make_uint2(t0, t1);
                *(uint2*)(pdst1 + kg * 8) = make_uint2(t2, t3);
            }
        }
        sum0 += __shfl_xor_sync(0xffffffffu, sum0, 1);
        sum0 += __shfl_xor_sync(0xffffffffu, sum0, 2);
        sum1 += __shfl_xor_sync(0xffffffffu, sum1, 1);
        sum1 += __shfl_xor_sync(0xffffffffu, sum1, 2);

        l0 = l0 * sc0 + sum0;  m0 = mn0;
        l1 = l1 * sc1 + sum1;  m1 = mn1;

        #pragma unroll
        for (int nf = 0; nf < 8; nf++) {
            o[nf][0] *= sc0; o[nf][1] *= sc0;
            o[nf][2] *= sc1; o[nf][3] *= sc1;
        }
        __syncwarp();   // Ps rows are warp-private

        // ---- O += P V (tf32 mma) ----
        #pragma unroll
        for (int ch = 0; ch < 8; ch++) {
            uint32_t pa[4];
            const int r0 = warp * 16 + g;
            pa[0] = Ps[(r0    ) * PAD + ch * 8 + c    ];
            pa[1] = Ps[(r0 + 8) * PAD + ch * 8 + c    ];
            pa[2] = Ps[(r0    ) * PAD + ch * 8 + c + 4];
            pa[3] = Ps[(r0 + 8) * PAD + ch * 8 + c + 4];
            const uint32_t* vb0 = &Vs[(ch * 8 + c    ) * PAD + g];
            const uint32_t* vb1 = &Vs[(ch * 8 + c + 4) * PAD + g];
            #pragma unroll
            for (int nf = 0; nf < 8; nf++)
                mma_tf32(o[nf], pa, vb0[nf * 8], vb1[nf * 8]);
        }
        __syncwarp();   // protect Ps before next-iteration overwrite path
    }

    // ---- epilogue: normalize, query-validity, store ----
    {
        const int r0 = warp * 16 + g;
        const int row0 = qt * 64 + r0, row1 = row0 + 8;
        float inv0 = (l0 > 0.f) ? (1.f / l0) : 0.f;
        float inv1 = (l1 > 0.f) ? (1.f / l1) : 0.f;
        if (pmask[b * SEQ + row0] == 0) inv0 = 0.f;
        if (pmask[b * SEQ + row1] == 0) inv1 = 0.f;
        float* out0 = attout + (rbase + row0) * HDIM + 2 * c;
        float* out1 = attout + (rbase + row1) * HDIM + 2 * c;
        #pragma unroll
        for (int nf = 0; nf < 8; nf++) {
            *(float2*)(out0 + nf * 8) = make_float2(o[nf][0] * inv0, o[nf][1] * inv0);
            *(float2*)(out1 + nf * 8) = make_float2(o[nf][2] * inv1, o[nf][3] * inv1);
        }
    }
}

// ---------------------------------------------------------------------------
extern "C" void kernel_launch(void* const* d_in, const int* in_sizes, int n_in,
                              void* d_out, int out_size) {
    const float* x     = (const float*)d_in[0];
    const int*   pmask = (const int*)d_in[2];
    const float* Wqkv  = (const float*)d_in[3];
    const float* Wout  = (const float*)d_in[4];
    float* out = (float*)d_out;

    float *qkv_p = nullptr, *att_p = nullptr;
    cudaGetSymbolAddress((void**)&qkv_p, g_qkv);
    cudaGetSymbolAddress((void**)&att_p, g_att);

    const int attn_smem = ATT_SMEM_WORDS * (int)sizeof(uint32_t);
    cudaFuncSetAttribute(attn_mma_kernel, cudaFuncAttributeMaxDynamicSharedMemorySize, attn_smem);

    // 1) QKV = x @ W_qkv : [8192,512] @ [512,1536]
    sgemm_kernel<<<dim3(QKVN / BN, ROWS / BM), 256>>>(x, Wqkv, qkv_p, ROWS, QKVN, DMODEL);

    // 2) tf32 tensor-core attention over the reshaped (flat) layout
    attn_mma_kernel<<<dim3(SEQ / 64, NHEAD, BATCH), 128, attn_smem>>>(qkv_p, pmask, att_p);

    // 3) out = att @ W_out : [8192,512] @ [512,512]
    sgemm_kernel<<<dim3(DMODEL / BN, ROWS / BM), 256>>>(att_p, Wout, out, ROWS, DMODEL, DMODEL);
}

// round 6
// speedup vs baseline: 2.5726x; 1.7435x over previous
#include <cuda_runtime.h>
#include <math.h>
#include <stdint.h>

#define BATCH   4
#define SEQ     2048
#define DMODEL  512
#define NHEAD   8
#define HDIM    64
#define ROWS    (BATCH * SEQ)        /* 8192 */
#define QKVN    (3 * DMODEL)         /* 1536 */

// Scratch (allocation-free rule: device globals)
__device__ float g_qkv[(size_t)ROWS * QKVN];     // [8192, 1536]
__device__ float g_att[(size_t)ROWS * DMODEL];   // [8192, 512] == (B,H,S,hd) flat

__device__ __forceinline__ uint32_t f2tf(float x) {
    uint32_t r;
    asm("cvt.rna.tf32.f32 %0, %1;" : "=r"(r) : "f"(x));
    return r;
}

__device__ __forceinline__ void mma_tf32(float c[4], const uint32_t a[4],
                                         uint32_t b0, uint32_t b1) {
    asm volatile(
        "mma.sync.aligned.m16n8k8.row.col.f32.tf32.tf32.f32 "
        "{%0,%1,%2,%3}, {%4,%5,%6,%7}, {%8,%9}, {%0,%1,%2,%3};"
        : "+f"(c[0]), "+f"(c[1]), "+f"(c[2]), "+f"(c[3])
        : "r"(a[0]), "r"(a[1]), "r"(a[2]), "r"(a[3]), "r"(b0), "r"(b1));
}

// ---------------------------------------------------------------------------
// TF32 tensor-core GEMM: C[M,N] = A[M,K] @ B[K,N], row-major fp32 in/out.
// 128x128x16 block tile, 256 threads = 8 warps (2x4), 64x32 warp tile.
// Operands staged in smem as pre-converted tf32 bits.
// ---------------------------------------------------------------------------
#define GBM 128
#define GBN 128
#define GBK 16
#define APAD 20    /* As row stride (words) */
#define BPAD 136   /* Bs row stride (words) */

__global__ __launch_bounds__(256)
void tf32_gemm_kernel(const float* __restrict__ A, const float* __restrict__ B,
                      float* __restrict__ C, int M, int N, int K) {
    __shared__ uint32_t As[GBM * APAD];   // [m][k] tf32
    __shared__ uint32_t Bs[GBK * BPAD];   // [k][n] tf32

    const int tid  = threadIdx.x;
    const int warp = tid >> 5;
    const int lane = tid & 31;
    const int g = lane >> 2;
    const int c = lane & 3;
    const int wm = warp >> 2;     // 0..1
    const int wn = warp & 3;      // 0..3

    // loaders: A 128x16 (2 thr/row, 8 floats), B 16x128 (16 thr/row, 8 floats)
    const int arow = tid >> 1, acol = (tid & 1) << 3;
    const int brow = tid >> 4, bcol = (tid & 15) << 3;

    const float* Ab = A + (size_t)(blockIdx.y * GBM + arow) * K + acol;
    const float* Bb = B + (size_t)brow * N + blockIdx.x * GBN + bcol;

    float acc[4][4][4];
    #pragma unroll
    for (int mf = 0; mf < 4; mf++)
        #pragma unroll
        for (int nf = 0; nf < 4; nf++)
            #pragma unroll
            for (int j = 0; j < 4; j++) acc[mf][nf][j] = 0.f;

    for (int k0 = 0; k0 < K; k0 += GBK) {
        // ---- stage tiles (tf32 converted) ----
        {
            float4 a0 = *(const float4*)(Ab + k0);
            float4 a1 = *(const float4*)(Ab + k0 + 4);
            uint32_t* da = &As[arow * APAD + acol];
            da[0] = f2tf(a0.x); da[1] = f2tf(a0.y); da[2] = f2tf(a0.z); da[3] = f2tf(a0.w);
            da[4] = f2tf(a1.x); da[5] = f2tf(a1.y); da[6] = f2tf(a1.z); da[7] = f2tf(a1.w);
            float4 b0 = *(const float4*)(Bb + (size_t)k0 * N);
            float4 b1 = *(const float4*)(Bb + (size_t)k0 * N + 4);
            uint32_t* db = &Bs[brow * BPAD + bcol];
            db[0] = f2tf(b0.x); db[1] = f2tf(b0.y); db[2] = f2tf(b0.z); db[3] = f2tf(b0.w);
            db[4] = f2tf(b1.x); db[5] = f2tf(b1.y); db[6] = f2tf(b1.z); db[7] = f2tf(b1.w);
        }
        __syncthreads();

        // ---- compute ----
        #pragma unroll
        for (int kk = 0; kk < GBK; kk += 8) {
            uint32_t af[4][4], bf0[4], bf1[4];
            #pragma unroll
            for (int mf = 0; mf < 4; mf++) {
                const int r0 = wm * 64 + mf * 16 + g;
                af[mf][0] = As[(r0    ) * APAD + kk + c    ];
                af[mf][1] = As[(r0 + 8) * APAD + kk + c    ];
                af[mf][2] = As[(r0    ) * APAD + kk + c + 4];
                af[mf][3] = As[(r0 + 8) * APAD + kk + c + 4];
            }
            #pragma unroll
            for (int nf = 0; nf < 4; nf++) {
                const int n = wn * 32 + nf * 8 + g;
                bf0[nf] = Bs[(kk + c    ) * BPAD + n];
                bf1[nf] = Bs[(kk + c + 4) * BPAD + n];
            }
            #pragma unroll
            for (int mf = 0; mf < 4; mf++)
                #pragma unroll
                for (int nf = 0; nf < 4; nf++)
                    mma_tf32(acc[mf][nf], af[mf], bf0[nf], bf1[nf]);
        }
        __syncthreads();
    }

    // ---- epilogue ----
    #pragma unroll
    for (int mf = 0; mf < 4; mf++) {
        const int r0 = blockIdx.y * GBM + wm * 64 + mf * 16 + g;
        #pragma unroll
        for (int nf = 0; nf < 4; nf++) {
            const int col = blockIdx.x * GBN + wn * 32 + nf * 8 + 2 * c;
            *(float2*)&C[(size_t)r0 * N + col] =
                make_float2(acc[mf][nf][0], acc[mf][nf][1]);
            *(float2*)&C[(size_t)(r0 + 8) * N + col] =
                make_float2(acc[mf][nf][2], acc[mf][nf][3]);
        }
    }
}

// ---------------------------------------------------------------------------
// TF32 tensor-core flash attention. Block = 256 threads (8 warps), 128
// queries of one (b,h'); streams 64-key tiles. Warp w owns query rows
// [16w,16w+16). Operands staged in smem as tf32 bits (pad=72, conflict-free).
// P round-trips through smem warp-locally (reuses Q region).
// ---------------------------------------------------------------------------
#define PAD 72
#define QT  128
#define ATT_SMEM_WORDS (QT * PAD + 2 * 64 * PAD + 64)

__global__ __launch_bounds__(256)
void attn_mma_kernel(const float* __restrict__ qkv, const int* __restrict__ pmask,
                     float* __restrict__ attout) {
    extern __shared__ uint32_t smu[];
    uint32_t* Qs = smu;                  // [QT][PAD]; later reused as Ps
    uint32_t* Ks = Qs + QT * PAD;        // [64][PAD]
    uint32_t* Vs = Ks + 64 * PAD;        // [64][PAD]
    float*    mk = (float*)(Vs + 64 * PAD);  // [64]

    const int qt = blockIdx.x, h = blockIdx.y, b = blockIdx.z;
    const int tid  = threadIdx.x;
    const int warp = tid >> 5;
    const int lane = tid & 31;
    const int g = lane >> 2;
    const int c = lane & 3;

    const size_t rbase = (size_t)b * (NHEAD * SEQ) + (size_t)h * SEQ;
    const float* qkv_b = qkv + rbase * (3 * HDIM);

    // Q loader: 2 thr/row (128 rows), 32 floats each
    const int qrow  = tid >> 1;
    const int qhalf = (tid & 1) * 32;
    // KV loader: 4 thr/row (64 rows), 16 floats each
    const int lrow = tid >> 2;
    const int lcol = (tid & 3) << 4;

    // ---- stage Q tile as tf32 ----
    {
        const float* src = qkv_b + (size_t)(qt * QT + qrow) * (3 * HDIM) + qhalf;
        uint32_t* dst = &Qs[qrow * PAD + qhalf];
        #pragma unroll
        for (int u = 0; u < 8; u++) {
            float4 v = *(const float4*)(src + 4 * u);
            dst[4*u+0] = f2tf(v.x); dst[4*u+1] = f2tf(v.y);
            dst[4*u+2] = f2tf(v.z); dst[4*u+3] = f2tf(v.w);
        }
    }
    __syncthreads();

    // ---- Q fragments ----
    uint32_t qa[8][4];
    {
        const int r0 = warp * 16 + g;
        #pragma unroll
        for (int ch = 0; ch < 8; ch++) {
            qa[ch][0] = Qs[(r0    ) * PAD + ch * 8 + c    ];
            qa[ch][1] = Qs[(r0 + 8) * PAD + ch * 8 + c    ];
            qa[ch][2] = Qs[(r0    ) * PAD + ch * 8 + c + 4];
            qa[ch][3] = Qs[(r0 + 8) * PAD + ch * 8 + c + 4];
        }
    }

    float o[8][4];
    #pragma unroll
    for (int nf = 0; nf < 8; nf++)
        #pragma unroll
        for (int j = 0; j < 4; j++) o[nf][j] = 0.f;
    float m0 = -INFINITY, m1 = -INFINITY, l0 = 0.f, l1 = 0.f;

    uint32_t* Ps = Qs;  // reuse after Q frags are in registers

    for (int kt = 0; kt < SEQ / 64; kt++) {
        __syncthreads();   // prior-iteration reads of Ks/Vs/mk complete
                           // (also: all warps took Q frags before first Ps write)

        // ---- stage K, V tiles (tf32) + mask ----
        {
            const float* srck = qkv_b + (size_t)(kt * 64 + lrow) * (3 * HDIM) + HDIM + lcol;
            const float* srcv = srck + HDIM;
            uint32_t* dk = &Ks[lrow * PAD + lcol];
            uint32_t* dv = &Vs[lrow * PAD + lcol];
            #pragma unroll
            for (int u = 0; u < 4; u++) {
                float4 kv = *(const float4*)(srck + 4 * u);
                dk[4*u+0] = f2tf(kv.x); dk[4*u+1] = f2tf(kv.y);
                dk[4*u+2] = f2tf(kv.z); dk[4*u+3] = f2tf(kv.w);
                float4 vv = *(const float4*)(srcv + 4 * u);
                dv[4*u+0] = f2tf(vv.x); dv[4*u+1] = f2tf(vv.y);
                dv[4*u+2] = f2tf(vv.z); dv[4*u+3] = f2tf(vv.w);
            }
            if (tid < 64)
                mk[tid] = (pmask[b * SEQ + kt * 64 + tid] != 0) ? 0.f : -INFINITY;
        }
        __syncthreads();

        // ---- S = Q K^T ----
        float s[8][4];
        #pragma unroll
        for (int kg = 0; kg < 8; kg++) {
            s[kg][0] = s[kg][1] = s[kg][2] = s[kg][3] = 0.f;
            const uint32_t* kbase = &Ks[(kg * 8 + g) * PAD + c];
            #pragma unroll
            for (int ch = 0; ch < 8; ch++)
                mma_tf32(s[kg], qa[ch], kbase[ch * 8], kbase[ch * 8 + 4]);
        }

        // ---- scale + mask ----
        #pragma unroll
        for (int kg = 0; kg < 8; kg++) {
            const int col0 = kg * 8 + 2 * c;
            float mk0 = mk[col0], mk1 = mk[col0 + 1];
            s[kg][0] = s[kg][0] * 0.125f + mk0;
            s[kg][1] = s[kg][1] * 0.125f + mk1;
            s[kg][2] = s[kg][2] * 0.125f + mk0;
            s[kg][3] = s[kg][3] * 0.125f + mk1;
        }

        // ---- online softmax ----
        float mx0 = -INFINITY, mx1 = -INFINITY;
        #pragma unroll
        for (int kg = 0; kg < 8; kg++) {
            mx0 = fmaxf(mx0, fmaxf(s[kg][0], s[kg][1]));
            mx1 = fmaxf(mx1, fmaxf(s[kg][2], s[kg][3]));
        }
        mx0 = fmaxf(mx0, __shfl_xor_sync(0xffffffffu, mx0, 1));
        mx0 = fmaxf(mx0, __shfl_xor_sync(0xffffffffu, mx0, 2));
        mx1 = fmaxf(mx1, __shfl_xor_sync(0xffffffffu, mx1, 1));
        mx1 = fmaxf(mx1, __shfl_xor_sync(0xffffffffu, mx1, 2));

        float mn0 = fmaxf(m0, mx0), mn1 = fmaxf(m1, mx1);
        float sc0 = (mn0 == -INFINITY) ? 1.f : __expf(m0 - mn0);
        float sc1 = (mn1 == -INFINITY) ? 1.f : __expf(m1 - mn1);

        float sum0 = 0.f, sum1 = 0.f;
        {
            const int r0 = warp * 16 + g;
            uint32_t* pdst0 = &Ps[(r0    ) * PAD + 2 * c];
            uint32_t* pdst1 = &Ps[(r0 + 8) * PAD + 2 * c];
            #pragma unroll
            for (int kg = 0; kg < 8; kg++) {
                float p0 = (s[kg][0] == -INFINITY) ? 0.f : __expf(s[kg][0] - mn0);
                float p1 = (s[kg][1] == -INFINITY) ? 0.f : __expf(s[kg][1] - mn0);
                float p2 = (s[kg][2] == -INFINITY) ? 0.f : __expf(s[kg][2] - mn1);
                float p3 = (s[kg][3] == -INFINITY) ? 0.f : __expf(s[kg][3] - mn1);
                uint32_t t0 = f2tf(p0), t1 = f2tf(p1), t2 = f2tf(p2), t3 = f2tf(p3);
                sum0 += __uint_as_float(t0) + __uint_as_float(t1);
                sum1 += __uint_as_float(t2) + __uint_as_float(t3);
                *(uint2*)(pdst0 + kg * 8) = make_uint2(t0, t1);
                *(uint2*)(pdst1 + kg * 8) = make_uint2(t2, t3);
            }
        }
        sum0 += __shfl_xor_sync(0xffffffffu, sum0, 1);
        sum0 += __shfl_xor_sync(0xffffffffu, sum0, 2);
        sum1 += __shfl_xor_sync(0xffffffffu, sum1, 1);
        sum1 += __shfl_xor_sync(0xffffffffu, sum1, 2);

        l0 = l0 * sc0 + sum0;  m0 = mn0;
        l1 = l1 * sc1 + sum1;  m1 = mn1;

        #pragma unroll
        for (int nf = 0; nf < 8; nf++) {
            o[nf][0] *= sc0; o[nf][1] *= sc0;
            o[nf][2] *= sc1; o[nf][3] *= sc1;
        }
        __syncwarp();   // Ps rows are warp-private

        // ---- O += P V ----
        #pragma unroll
        for (int ch = 0; ch < 8; ch++) {
            uint32_t pa[4];
            const int r0 = warp * 16 + g;
            pa[0] = Ps[(r0    ) * PAD + ch * 8 + c    ];
            pa[1] = Ps[(r0 + 8) * PAD + ch * 8 + c    ];
            pa[2] = Ps[(r0    ) * PAD + ch * 8 + c + 4];
            pa[3] = Ps[(r0 + 8) * PAD + ch * 8 + c + 4];
            const uint32_t* vb0 = &Vs[(ch * 8 + c    ) * PAD + g];
            const uint32_t* vb1 = &Vs[(ch * 8 + c + 4) * PAD + g];
            #pragma unroll
            for (int nf = 0; nf < 8; nf++)
                mma_tf32(o[nf], pa, vb0[nf * 8], vb1[nf * 8]);
        }
        __syncwarp();
    }

    // ---- epilogue ----
    {
        const int r0 = warp * 16 + g;
        const int row0 = qt * QT + r0, row1 = row0 + 8;
        float inv0 = (l0 > 0.f) ? (1.f / l0) : 0.f;
        float inv1 = (l1 > 0.f) ? (1.f / l1) : 0.f;
        if (pmask[b * SEQ + row0] == 0) inv0 = 0.f;
        if (pmask[b * SEQ + row1] == 0) inv1 = 0.f;
        float* out0 = attout + (rbase + row0) * HDIM + 2 * c;
        float* out1 = attout + (rbase + row1) * HDIM + 2 * c;
        #pragma unroll
        for (int nf = 0; nf < 8; nf++) {
            *(float2*)(out0 + nf * 8) = make_float2(o[nf][0] * inv0, o[nf][1] * inv0);
            *(float2*)(out1 + nf * 8) = make_float2(o[nf][2] * inv1, o[nf][3] * inv1);
        }
    }
}

// ---------------------------------------------------------------------------
extern "C" void kernel_launch(void* const* d_in, const int* in_sizes, int n_in,
                              void* d_out, int out_size) {
    const float* x     = (const float*)d_in[0];
    const int*   pmask = (const int*)d_in[2];
    const float* Wqkv  = (const float*)d_in[3];
    const float* Wout  = (const float*)d_in[4];
    float* out = (float*)d_out;

    float *qkv_p = nullptr, *att_p = nullptr;
    cudaGetSymbolAddress((void**)&qkv_p, g_qkv);
    cudaGetSymbolAddress((void**)&att_p, g_att);

    const int attn_smem = ATT_SMEM_WORDS * (int)sizeof(uint32_t);
    cudaFuncSetAttribute(attn_mma_kernel, cudaFuncAttributeMaxDynamicSharedMemorySize, attn_smem);

    // 1) QKV = x @ W_qkv : [8192,512] @ [512,1536]
    tf32_gemm_kernel<<<dim3(QKVN / GBN, ROWS / GBM), 256>>>(x, Wqkv, qkv_p, ROWS, QKVN, DMODEL);

    // 2) tf32 tensor-core attention over the reshaped (flat) layout
    attn_mma_kernel<<<dim3(SEQ / QT, NHEAD, BATCH), 256, attn_smem>>>(qkv_p, pmask, att_p);

    // 3) out = att @ W_out : [8192,512] @ [512,512]
    tf32_gemm_kernel<<<dim3(DMODEL / GBN, ROWS / GBM), 256>>>(att_p, Wout, out, ROWS, DMODEL, DMODEL);
}